// round 14
// baseline (speedup 1.0000x reference)
#include <cuda_runtime.h>
#include <cuda_fp16.h>

#define NN 50000
#define EE 1600000
#define HD 128
#define H2 64             // HD/2 half2 per row
#define GG 512
#define OUTD 10
#define KSTEPS 10
#define ALPHA 0.1f
#define NB 196            // ceil(NN/256)
// Per-step storage rescale: y_k = x_k / 4^k  (exact power of 2)
#define WS (0.9f / 4.0f)          // folded into edge weights
#define OSCALE 1048576.0f         // 4^10 = 2^20, applied at the final step

// packed dual-fp32 FMA (sm_103a FFMA2) — bit-exact fp32, 2 MACs/instr
#define FMA_F32X2(acc, a, b) \
    asm("fma.rn.f32x2 %0, %1, %2, %3;" : "=l"(acc) : "l"(a), "l"(b), "l"(acc))
#define PACK_F32X2(out, lo, hi) \
    asm("mov.b64 %0, {%1, %2};" : "=l"(out) : "f"(lo), "f"(hi))
#define UNPACK_F32X2(lo, hi, in) \
    asm("mov.b64 {%0, %1}, %2;" : "=f"(lo), "=f"(hi) : "l"(in))

// Scratch (device globals; no dynamic allocation allowed).
// g_deg is zero at module load and re-zeroed at the TAIL of every launch,
// so each launch (first run, capture, every replay) sees zeros.
__device__ __half2 g_ah16[NN * H2];  // ALPHA * x0, fp16 (teleport term)
__device__ __half2 g_x16a[NN * H2];  // ping (scaled fp16 iterate)
__device__ __half2 g_x16b[NN * H2];  // pong
__device__ float   g_Wc[HD * HD];    // fused W1@W2
__device__ float   g_bc[HD];         // fused b1@W2 + b2
__device__ float   g_pooled[GG * HD];

__device__ int  g_deg[NN];           // zero-init + tail re-zero
__device__ int  g_cursor[NN];
__device__ int  g_rowptr[NN + 1];
__device__ int2 g_sw[EE];            // packed (src, weight-bits)

// ---------------------------------------------------------------------------
// Fuse the two stacked linears: Wc = W1 @ W2, bc = b1 @ W2 + b2
// ---------------------------------------------------------------------------
__global__ void k_wc(const float* __restrict__ W1, const float* __restrict__ b1,
                     const float* __restrict__ W2, const float* __restrict__ b2) {
    int h = threadIdx.x;
    int d0 = blockIdx.x * 8;
    for (int d = d0; d < d0 + 8; ++d) {
        float s = 0.f;
        #pragma unroll 8
        for (int k = 0; k < HD; ++k) s += W1[d * HD + k] * W2[k * HD + h];
        g_Wc[d * HD + h] = s;
    }
    if (blockIdx.x == 0) {
        float s = b2[h];
        #pragma unroll 8
        for (int k = 0; k < HD; ++k) s += b1[k] * W2[k * HD + h];
        g_bc[h] = s;
    }
}

// ---------------------------------------------------------------------------
// x0 = F^T @ Wc + bc.  Writes fp16 y0 = x0 and fp16 ALPHA*x0.
// ---------------------------------------------------------------------------
__global__ __launch_bounds__(256) void k_x0(const float* __restrict__ F) {
    __shared__ float Fs[32][64];
    __shared__ float Ws[32][128];
    int t  = threadIdx.x;
    int nb = blockIdx.x * 64;
    int n0 = (t & 15) * 4;
    int h0 = (t >> 4) * 8;

    unsigned long long accp[4][4];
    #pragma unroll
    for (int i = 0; i < 4; ++i)
        #pragma unroll
        for (int j = 0; j < 4; ++j) accp[i][j] = 0ull;

    for (int c = 0; c < 4; ++c) {
        __syncthreads();
        for (int i = t; i < 32 * 64; i += 256) {
            int dd = i >> 6, nn = i & 63, n = nb + nn;
            Fs[dd][nn] = (n < NN) ? F[(c * 32 + dd) * NN + n] : 0.f;
        }
        for (int i = t; i < 32 * 128; i += 256) {
            int dd = i >> 7, hh = i & 127;
            Ws[dd][hh] = g_Wc[(c * 32 + dd) * HD + hh];
        }
        __syncthreads();
        #pragma unroll
        for (int d = 0; d < 32; ++d) {
            float4 fa = *(const float4*)&Fs[d][n0];
            ulonglong2 wa = *(const ulonglong2*)&Ws[d][h0];
            ulonglong2 wb = *(const ulonglong2*)&Ws[d][h0 + 4];
            unsigned long long wp[4] = {wa.x, wa.y, wb.x, wb.y};
            float f[4] = {fa.x, fa.y, fa.z, fa.w};
            #pragma unroll
            for (int i = 0; i < 4; ++i) {
                unsigned long long fp;
                PACK_F32X2(fp, f[i], f[i]);
                #pragma unroll
                for (int j = 0; j < 4; ++j) FMA_F32X2(accp[i][j], fp, wp[j]);
            }
        }
    }
    #pragma unroll
    for (int i = 0; i < 4; ++i) {
        int n = nb + n0 + i;
        if (n < NN) {
            float o[8];
            #pragma unroll
            for (int j = 0; j < 4; ++j) {
                float lo, hi;
                UNPACK_F32X2(lo, hi, accp[i][j]);
                o[2 * j]     = lo + g_bc[h0 + 2 * j];
                o[2 * j + 1] = hi + g_bc[h0 + 2 * j + 1];
            }
            #pragma unroll
            for (int j = 0; j < 8; j += 4) {
                __half2 p0 = __floats2half2_rn(o[j],     o[j + 1]);
                __half2 p1 = __floats2half2_rn(o[j + 2], o[j + 3]);
                *(uint2*)&g_x16a[n * H2 + (h0 + j) / 2] =
                    make_uint2(*(unsigned*)&p0, *(unsigned*)&p1);
                __half2 a0 = __floats2half2_rn(ALPHA * o[j],     ALPHA * o[j + 1]);
                __half2 a1 = __floats2half2_rn(ALPHA * o[j + 2], ALPHA * o[j + 3]);
                *(uint2*)&g_ah16[n * H2 + (h0 + j) / 2] =
                    make_uint2(*(unsigned*)&a0, *(unsigned*)&a1);
            }
        }
    }
}

// ---------------------------------------------------------------------------
// CSR construction: hist (MLP8) -> single-block scan -> scatter (MLP4)
// ---------------------------------------------------------------------------
__global__ __launch_bounds__(256) void k_hist(const int* __restrict__ ei) {
    int e0 = blockIdx.x * 2048 + threadIdx.x;
    #pragma unroll
    for (int k = 0; k < 8; ++k) {
        int e = e0 + k * 256;
        if (e < EE) atomicAdd(&g_deg[__ldg(&ei[EE + e])], 1);
    }
}

// One block, 1024 threads: full exclusive scan of g_deg -> rowptr + cursor.
__global__ __launch_bounds__(1024) void k_scan_all() {
    __shared__ int sums[1024];
    int t = threadIdx.x;
    const int CH = 49;                 // 1024*49 = 50176 >= NN
    int start = t * CH;
    int s = 0;
    for (int i = 0; i < CH; ++i) {
        int idx = start + i;
        if (idx < NN) s += g_deg[idx];
    }
    sums[t] = s;
    __syncthreads();
    for (int off = 1; off < 1024; off <<= 1) {
        int u = (t >= off) ? sums[t - off] : 0;
        __syncthreads();
        sums[t] += u;
        __syncthreads();
    }
    int run = sums[t] - s;             // exclusive prefix of this chunk
    for (int i = 0; i < CH; ++i) {
        int idx = start + i;
        if (idx < NN) {
            g_rowptr[idx] = run;
            g_cursor[idx] = run;
            run += g_deg[idx];         // L1/L2 hot re-read
        }
    }
    if (t == 1023) g_rowptr[NN] = EE;
}

// 4 edges per thread — independent ATOMG chains hide the ~318cyc latency.
__global__ __launch_bounds__(256) void k_scatter(const int*   __restrict__ ei,
                                                 const float* __restrict__ ew) {
    int e0 = blockIdx.x * 1024 + threadIdx.x;
    int dst[4], pos[4];
    float w[4];
    #pragma unroll
    for (int k = 0; k < 4; ++k) {
        int e = e0 + k * 256;
        if (e < EE) {
            dst[k] = __ldg(&ei[EE + e]);
            w[k]   = WS * __ldg(&ew[e]);
        } else dst[k] = -1;
    }
    #pragma unroll
    for (int k = 0; k < 4; ++k)
        if (dst[k] >= 0) pos[k] = atomicAdd(&g_cursor[dst[k]], 1);
    #pragma unroll
    for (int k = 0; k < 4; ++k) {
        int e = e0 + k * 256;
        if (dst[k] >= 0)
            g_sw[pos[k]] = make_int2(__ldg(&ei[e]), __float_as_int(w[k]));
    }
}

// Tail: re-zero g_deg for the next launch/replay (invariant restore).
__global__ void k_zero_deg_tail() {
    int i = blockIdx.x * 256 + threadIdx.x;
    if (i < NN) g_deg[i] = 0;
}

// Zero g_pooled (runs on s2, off the CSR critical path).
__global__ void k_zero_pool() {
    int i = blockIdx.x * 256 + threadIdx.x;   // GG*HD = 65536 exact
    g_pooled[i] = 0.f;
}

// ---------------------------------------------------------------------------
// Propagation, atomic-free, scaled-fp16 gather: one warp per dst node,
// lane owns 4 columns (2 half2). fp32 accumulate. Uniform LDG broadcast.
//   y_out[n] = sum_e (0.9/4)*w_e*y_in[src_e] + hs*(ALPHA*x0)[n]
// final: pooled[batch[n]] += OSCALE * y_out[n]
// ---------------------------------------------------------------------------
__global__ __launch_bounds__(256) void k_prop(const __half2* __restrict__ xin,
                                              __half2* __restrict__ xout,
                                              float hs, int final_step,
                                              const int* __restrict__ batch) {
    unsigned warp = (blockIdx.x * 256u + threadIdx.x) >> 5;
    if (warp >= NN) return;
    int lane = threadIdx.x & 31;
    int beg = g_rowptr[warp];
    int end = g_rowptr[warp + 1];

    float4 acc = make_float4(0.f, 0.f, 0.f, 0.f);
    #pragma unroll 4
    for (int j = beg; j < end; ++j) {
        int2 sw = __ldg(&g_sw[j]);                 // uniform across warp
        float w = __int_as_float(sw.y);
        uint2 p = __ldg((const uint2*)&xin[sw.x * H2 + lane * 2]);
        float2 v0 = __half22float2(*(__half2*)&p.x);
        float2 v1 = __half22float2(*(__half2*)&p.y);
        acc.x += w * v0.x;
        acc.y += w * v0.y;
        acc.z += w * v1.x;
        acc.w += w * v1.y;
    }
    uint2 hp = *(const uint2*)&g_ah16[warp * H2 + lane * 2];
    float2 h0 = __half22float2(*(__half2*)&hp.x);
    float2 h1 = __half22float2(*(__half2*)&hp.y);
    float4 o = make_float4(acc.x + hs * h0.x, acc.y + hs * h0.y,
                           acc.z + hs * h1.x, acc.w + hs * h1.y);
    if (final_step) {
        int g = __ldg(&batch[warp]);
        atomicAdd((float4*)&g_pooled[g * HD + lane * 4],
                  make_float4(OSCALE * o.x, OSCALE * o.y,
                              OSCALE * o.z, OSCALE * o.w));
    } else {
        __half2 p0 = __floats2half2_rn(o.x, o.y);
        __half2 p1 = __floats2half2_rn(o.z, o.w);
        *(uint2*)&xout[warp * H2 + lane * 2] =
            make_uint2(*(unsigned*)&p0, *(unsigned*)&p1);
    }
}

// ---------------------------------------------------------------------------
// Head: relu(pooled @ V0w + V0b) @ V1w + V1b -> log_softmax
// ---------------------------------------------------------------------------
__global__ __launch_bounds__(128) void k_head(const float* __restrict__ V0w,
                                              const float* __restrict__ V0b,
                                              const float* __restrict__ V1w,
                                              const float* __restrict__ V1b,
                                              float* __restrict__ out) {
    int g = blockIdx.x, t = threadIdx.x;
    __shared__ float p[HD];
    __shared__ float hid[HD];
    __shared__ float y[OUTD];
    p[t] = g_pooled[g * HD + t];
    __syncthreads();
    float a = V0b[t];
    #pragma unroll 8
    for (int d = 0; d < HD; ++d) a += p[d] * V0w[d * HD + t];
    hid[t] = fmaxf(a, 0.f);
    __syncthreads();
    if (t < OUTD) {
        float s = V1b[t];
        #pragma unroll 8
        for (int hh = 0; hh < HD; ++hh) s += hid[hh] * V1w[hh * OUTD + t];
        y[t] = s;
    }
    __syncthreads();
    if (t < OUTD) {
        float m = y[0];
        #pragma unroll
        for (int o = 1; o < OUTD; ++o) m = fmaxf(m, y[o]);
        float s = 0.f;
        #pragma unroll
        for (int o = 0; o < OUTD; ++o) s += expf(y[o] - m);
        out[g * OUTD + t] = y[t] - m - logf(s);
    }
}

// ---------------------------------------------------------------------------
extern "C" void kernel_launch(void* const* d_in, const int* in_sizes, int n_in,
                              void* d_out, int out_size) {
    const float* features    = (const float*)d_in[0];
    const float* edge_weight = (const float*)d_in[1];
    const float* W1          = (const float*)d_in[2];
    const float* b1          = (const float*)d_in[3];
    const float* W2          = (const float*)d_in[4];
    const float* b2          = (const float*)d_in[5];
    const float* V0w         = (const float*)d_in[6];
    const float* V0b         = (const float*)d_in[7];
    const float* V1w         = (const float*)d_in[8];
    const float* V1b         = (const float*)d_in[9];
    const int*   edge_index  = (const int*)d_in[10];
    const int*   batch       = (const int*)d_in[11];
    float*       out         = (float*)d_out;

    // One-time host-side stream/event setup (no device allocations).
    static cudaStream_t s2 = nullptr;
    static cudaEvent_t evFork = nullptr, evJoin = nullptr;
    if (s2 == nullptr) {
        cudaStreamCreateWithFlags(&s2, cudaStreamNonBlocking);
        cudaEventCreateWithFlags(&evFork, cudaEventDisableTiming);
        cudaEventCreateWithFlags(&evJoin, cudaEventDisableTiming);
    }

    // Fork: dense front-end + pool-zero on s2; CSR build on the main stream.
    cudaEventRecord(evFork, 0);
    cudaStreamWaitEvent(s2, evFork, 0);
    k_wc<<<16, 128, 0, s2>>>(W1, b1, W2, b2);
    k_x0<<<(NN + 63) / 64, 256, 0, s2>>>(features);
    k_zero_pool<<<256, 256, 0, s2>>>();
    cudaEventRecord(evJoin, s2);

    // CSR build (main stream; g_deg arrives zeroed from the previous
    // launch's tail — or from static zero-init on the very first call).
    k_hist<<<(EE + 2047) / 2048, 256>>>(edge_index);
    k_scan_all<<<1, 1024>>>();
    k_scatter<<<(EE + 1023) / 1024, 256>>>(edge_index, edge_weight);

    // Join before propagation (needs both CSR and x0/ah16/pooled-zero)
    cudaStreamWaitEvent(0, evJoin, 0);

    // APPNP propagation (scaled fp16 iterate); final step fuses the pooling.
    __half2* xa = nullptr; __half2* xb = nullptr;
    cudaGetSymbolAddress((void**)&xa, g_x16a);
    cudaGetSymbolAddress((void**)&xb, g_x16b);

    const int prop_grid = (NN * 32 + 255) / 256;   // 6250
    const __half2* cur = xa;
    float hs = 1.0f;
    for (int k = 0; k < KSTEPS; ++k) {
        hs *= 0.25f;                     // 4^-(k+1); ALPHA folded into g_ah16
        int fin = (k == KSTEPS - 1);
        __half2* nxt = (k % 2 == 0) ? xb : xa;
        k_prop<<<prop_grid, 256>>>(cur, fin ? nullptr : nxt, hs, fin, batch);
        cur = nxt;
    }

    // Tail: restore the g_deg==0 invariant for the next launch/replay,
    // overlapped with the head on s2 (both depend on the last prop step).
    cudaEventRecord(evFork, 0);
    cudaStreamWaitEvent(s2, evFork, 0);
    k_zero_deg_tail<<<NB, 256, 0, s2>>>();
    cudaEventRecord(evJoin, s2);

    k_head<<<GG, 128>>>(V0w, V0b, V1w, V1b, out);
    cudaStreamWaitEvent(0, evJoin, 0);   // join so the graph ends cleanly
}

// round 15
// speedup vs baseline: 1.0378x; 1.0378x over previous
#include <cuda_runtime.h>
#include <cuda_fp16.h>

#define NN 50000
#define EE 1600000
#define HD 128
#define H2 64             // HD/2 half2 per row
#define GG 512
#define OUTD 10
#define KSTEPS 10
#define ALPHA 0.1f
#define NB 196            // ceil(NN/256)
// Per-step storage rescale: y_k = x_k / 4^k  (exact power of 2)
#define WS (0.9f / 4.0f)          // folded into edge weights
#define OSCALE 1048576.0f         // 4^10 = 2^20, applied at the final step

// packed dual-fp32 FMA (sm_103a FFMA2) — bit-exact fp32, 2 MACs/instr
#define FMA_F32X2(acc, a, b) \
    asm("fma.rn.f32x2 %0, %1, %2, %3;" : "=l"(acc) : "l"(a), "l"(b), "l"(acc))
#define PACK_F32X2(out, lo, hi) \
    asm("mov.b64 %0, {%1, %2};" : "=l"(out) : "f"(lo), "f"(hi))
#define UNPACK_F32X2(lo, hi, in) \
    asm("mov.b64 {%0, %1}, %2;" : "=f"(lo), "=f"(hi) : "l"(in))

// Scratch (device globals; no dynamic allocation allowed).
// g_deg starts zero (static init) and is re-zeroed on s2 each launch after
// its last reader, so every eager run / replay sees zeros at hist time.
__device__ __half2 g_ah16[NN * H2];  // ALPHA * x0, fp16 (teleport term)
__device__ __half2 g_x16a[NN * H2];  // ping (scaled fp16 iterate)
__device__ __half2 g_x16b[NN * H2];  // pong
__device__ float   g_Wc[HD * HD];    // fused W1@W2
__device__ float   g_bc[HD];         // fused b1@W2 + b2
__device__ float   g_pooled[GG * HD];

__device__ int  g_deg[NN];
__device__ int  g_cursor[NN];
__device__ int  g_rowptr[NN + 1];
__device__ int  g_bsum[NB];
__device__ int2 g_sw[EE];            // packed (src, weight-bits)

// ---------------------------------------------------------------------------
// Fuse the two stacked linears: Wc = W1 @ W2, bc = b1 @ W2 + b2
// ---------------------------------------------------------------------------
__global__ void k_wc(const float* __restrict__ W1, const float* __restrict__ b1,
                     const float* __restrict__ W2, const float* __restrict__ b2) {
    int h = threadIdx.x;
    int d0 = blockIdx.x * 8;
    for (int d = d0; d < d0 + 8; ++d) {
        float s = 0.f;
        #pragma unroll 8
        for (int k = 0; k < HD; ++k) s += W1[d * HD + k] * W2[k * HD + h];
        g_Wc[d * HD + h] = s;
    }
    if (blockIdx.x == 0) {
        float s = b2[h];
        #pragma unroll 8
        for (int k = 0; k < HD; ++k) s += b1[k] * W2[k * HD + h];
        g_bc[h] = s;
    }
}

// ---------------------------------------------------------------------------
// x0 = F^T @ Wc + bc.  Writes fp16 y0 = x0 and fp16 ALPHA*x0.
// ---------------------------------------------------------------------------
__global__ __launch_bounds__(256) void k_x0(const float* __restrict__ F) {
    __shared__ float Fs[32][64];
    __shared__ float Ws[32][128];
    int t  = threadIdx.x;
    int nb = blockIdx.x * 64;
    int n0 = (t & 15) * 4;
    int h0 = (t >> 4) * 8;

    unsigned long long accp[4][4];
    #pragma unroll
    for (int i = 0; i < 4; ++i)
        #pragma unroll
        for (int j = 0; j < 4; ++j) accp[i][j] = 0ull;

    for (int c = 0; c < 4; ++c) {
        __syncthreads();
        for (int i = t; i < 32 * 64; i += 256) {
            int dd = i >> 6, nn = i & 63, n = nb + nn;
            Fs[dd][nn] = (n < NN) ? F[(c * 32 + dd) * NN + n] : 0.f;
        }
        for (int i = t; i < 32 * 128; i += 256) {
            int dd = i >> 7, hh = i & 127;
            Ws[dd][hh] = g_Wc[(c * 32 + dd) * HD + hh];
        }
        __syncthreads();
        #pragma unroll
        for (int d = 0; d < 32; ++d) {
            float4 fa = *(const float4*)&Fs[d][n0];
            ulonglong2 wa = *(const ulonglong2*)&Ws[d][h0];
            ulonglong2 wb = *(const ulonglong2*)&Ws[d][h0 + 4];
            unsigned long long wp[4] = {wa.x, wa.y, wb.x, wb.y};
            float f[4] = {fa.x, fa.y, fa.z, fa.w};
            #pragma unroll
            for (int i = 0; i < 4; ++i) {
                unsigned long long fp;
                PACK_F32X2(fp, f[i], f[i]);
                #pragma unroll
                for (int j = 0; j < 4; ++j) FMA_F32X2(accp[i][j], fp, wp[j]);
            }
        }
    }
    #pragma unroll
    for (int i = 0; i < 4; ++i) {
        int n = nb + n0 + i;
        if (n < NN) {
            float o[8];
            #pragma unroll
            for (int j = 0; j < 4; ++j) {
                float lo, hi;
                UNPACK_F32X2(lo, hi, accp[i][j]);
                o[2 * j]     = lo + g_bc[h0 + 2 * j];
                o[2 * j + 1] = hi + g_bc[h0 + 2 * j + 1];
            }
            #pragma unroll
            for (int j = 0; j < 8; j += 4) {
                __half2 p0 = __floats2half2_rn(o[j],     o[j + 1]);
                __half2 p1 = __floats2half2_rn(o[j + 2], o[j + 3]);
                *(uint2*)&g_x16a[n * H2 + (h0 + j) / 2] =
                    make_uint2(*(unsigned*)&p0, *(unsigned*)&p1);
                __half2 a0 = __floats2half2_rn(ALPHA * o[j],     ALPHA * o[j + 1]);
                __half2 a1 = __floats2half2_rn(ALPHA * o[j + 2], ALPHA * o[j + 3]);
                *(uint2*)&g_ah16[n * H2 + (h0 + j) / 2] =
                    make_uint2(*(unsigned*)&a0, *(unsigned*)&a1);
            }
        }
    }
}

// ---------------------------------------------------------------------------
// CSR construction: hist -> blocksum -> rowptr(+inline boff, +zeropool)
//                   -> scatter;  deg re-zeroed on s2 afterwards.
// ---------------------------------------------------------------------------
__global__ __launch_bounds__(256) void k_hist(const int* __restrict__ ei) {
    int e0 = blockIdx.x * 1024 + threadIdx.x;
    #pragma unroll
    for (int k = 0; k < 4; ++k) {
        int e = e0 + k * 256;
        if (e < EE) atomicAdd(&g_deg[__ldg(&ei[EE + e])], 1);
    }
}

__global__ __launch_bounds__(256) void k_blocksum() {
    __shared__ int sm[256];
    int t = threadIdx.x;
    int i = blockIdx.x * 256 + t;
    sm[t] = (i < NN) ? g_deg[i] : 0;
    __syncthreads();
    for (int off = 128; off > 0; off >>= 1) {
        if (t < off) sm[t] += sm[t + off];
        __syncthreads();
    }
    if (t == 0) g_bsum[blockIdx.x] = sm[0];
}

// blocks [0, NB): rowptr + cursor (block offset computed inline from g_bsum);
// blocks [NB, NB+256): zero g_pooled
__global__ __launch_bounds__(256) void k_rowptr_zeropool() {
    int t = threadIdx.x;
    int b = blockIdx.x;
    if (b >= NB) {
        int i = (b - NB) * 256 + t;      // GG*HD = 65536 = 256*256 exact
        g_pooled[i] = 0.f;
        return;
    }
    __shared__ int pre[256];
    // inline exclusive block-offset: sum of g_bsum[0..b)
    pre[t] = (t < b) ? g_bsum[t] : 0;    // NB=196 <= 256
    __syncthreads();
    for (int off = 128; off > 0; off >>= 1) {
        if (t < off) pre[t] += pre[t + off];
        __syncthreads();
    }
    int boff = pre[0];
    __syncthreads();
    // intra-block inclusive scan of deg
    __shared__ int sm[256];
    int i = b * 256 + t;
    int v = (i < NN) ? g_deg[i] : 0;
    sm[t] = v;
    __syncthreads();
    for (int off = 1; off < 256; off <<= 1) {
        int u = (t >= off) ? sm[t - off] : 0;
        __syncthreads();
        sm[t] += u;
        __syncthreads();
    }
    int rp = boff + sm[t] - v;           // exclusive prefix
    if (i < NN) { g_rowptr[i] = rp; g_cursor[i] = rp; }
    if (b == 0 && t == 0) g_rowptr[NN] = EE;
}

// 4 edges per thread — independent ATOMG chains hide the ~318cyc latency.
__global__ __launch_bounds__(256) void k_scatter(const int*   __restrict__ ei,
                                                 const float* __restrict__ ew) {
    int e0 = blockIdx.x * 1024 + threadIdx.x;
    int dst[4], pos[4];
    float w[4];
    #pragma unroll
    for (int k = 0; k < 4; ++k) {
        int e = e0 + k * 256;
        if (e < EE) {
            dst[k] = __ldg(&ei[EE + e]);
            w[k]   = WS * __ldg(&ew[e]);
        } else dst[k] = -1;
    }
    #pragma unroll
    for (int k = 0; k < 4; ++k)
        if (dst[k] >= 0) pos[k] = atomicAdd(&g_cursor[dst[k]], 1);
    #pragma unroll
    for (int k = 0; k < 4; ++k) {
        int e = e0 + k * 256;
        if (dst[k] >= 0)
            g_sw[pos[k]] = make_int2(__ldg(&ei[e]), __float_as_int(w[k]));
    }
}

// Re-zero g_deg (runs on s2, after its last reader; invariant restore).
__global__ void k_zero_deg() {
    int i = blockIdx.x * 256 + threadIdx.x;
    if (i < NN) g_deg[i] = 0;
}

// ---------------------------------------------------------------------------
// Propagation, atomic-free, scaled-fp16 gather: one warp per dst node,
// lane owns 4 columns (2 half2). fp32 accumulate. Uniform LDG broadcast.
//   y_out[n] = sum_e (0.9/4)*w_e*y_in[src_e] + hs*(ALPHA*x0)[n]
// final: pooled[batch[n]] += OSCALE * y_out[n]
// ---------------------------------------------------------------------------
__global__ __launch_bounds__(256) void k_prop(const __half2* __restrict__ xin,
                                              __half2* __restrict__ xout,
                                              float hs, int final_step,
                                              const int* __restrict__ batch) {
    unsigned warp = (blockIdx.x * 256u + threadIdx.x) >> 5;
    if (warp >= NN) return;
    int lane = threadIdx.x & 31;
    int beg = g_rowptr[warp];
    int end = g_rowptr[warp + 1];

    float4 acc = make_float4(0.f, 0.f, 0.f, 0.f);
    #pragma unroll 4
    for (int j = beg; j < end; ++j) {
        int2 sw = __ldg(&g_sw[j]);                 // uniform across warp
        float w = __int_as_float(sw.y);
        uint2 p = __ldg((const uint2*)&xin[sw.x * H2 + lane * 2]);
        float2 v0 = __half22float2(*(__half2*)&p.x);
        float2 v1 = __half22float2(*(__half2*)&p.y);
        acc.x += w * v0.x;
        acc.y += w * v0.y;
        acc.z += w * v1.x;
        acc.w += w * v1.y;
    }
    uint2 hp = *(const uint2*)&g_ah16[warp * H2 + lane * 2];
    float2 h0 = __half22float2(*(__half2*)&hp.x);
    float2 h1 = __half22float2(*(__half2*)&hp.y);
    float4 o = make_float4(acc.x + hs * h0.x, acc.y + hs * h0.y,
                           acc.z + hs * h1.x, acc.w + hs * h1.y);
    if (final_step) {
        int g = __ldg(&batch[warp]);
        atomicAdd((float4*)&g_pooled[g * HD + lane * 4],
                  make_float4(OSCALE * o.x, OSCALE * o.y,
                              OSCALE * o.z, OSCALE * o.w));
    } else {
        __half2 p0 = __floats2half2_rn(o.x, o.y);
        __half2 p1 = __floats2half2_rn(o.z, o.w);
        *(uint2*)&xout[warp * H2 + lane * 2] =
            make_uint2(*(unsigned*)&p0, *(unsigned*)&p1);
    }
}

// ---------------------------------------------------------------------------
// Head: relu(pooled @ V0w + V0b) @ V1w + V1b -> log_softmax
// ---------------------------------------------------------------------------
__global__ __launch_bounds__(128) void k_head(const float* __restrict__ V0w,
                                              const float* __restrict__ V0b,
                                              const float* __restrict__ V1w,
                                              const float* __restrict__ V1b,
                                              float* __restrict__ out) {
    int g = blockIdx.x, t = threadIdx.x;
    __shared__ float p[HD];
    __shared__ float hid[HD];
    __shared__ float y[OUTD];
    p[t] = g_pooled[g * HD + t];
    __syncthreads();
    float a = V0b[t];
    #pragma unroll 8
    for (int d = 0; d < HD; ++d) a += p[d] * V0w[d * HD + t];
    hid[t] = fmaxf(a, 0.f);
    __syncthreads();
    if (t < OUTD) {
        float s = V1b[t];
        #pragma unroll 8
        for (int hh = 0; hh < HD; ++hh) s += hid[hh] * V1w[hh * OUTD + t];
        y[t] = s;
    }
    __syncthreads();
    if (t < OUTD) {
        float m = y[0];
        #pragma unroll
        for (int o = 1; o < OUTD; ++o) m = fmaxf(m, y[o]);
        float s = 0.f;
        #pragma unroll
        for (int o = 0; o < OUTD; ++o) s += expf(y[o] - m);
        out[g * OUTD + t] = y[t] - m - logf(s);
    }
}

// ---------------------------------------------------------------------------
extern "C" void kernel_launch(void* const* d_in, const int* in_sizes, int n_in,
                              void* d_out, int out_size) {
    const float* features    = (const float*)d_in[0];
    const float* edge_weight = (const float*)d_in[1];
    const float* W1          = (const float*)d_in[2];
    const float* b1          = (const float*)d_in[3];
    const float* W2          = (const float*)d_in[4];
    const float* b2          = (const float*)d_in[5];
    const float* V0w         = (const float*)d_in[6];
    const float* V0b         = (const float*)d_in[7];
    const float* V1w         = (const float*)d_in[8];
    const float* V1b         = (const float*)d_in[9];
    const int*   edge_index  = (const int*)d_in[10];
    const int*   batch       = (const int*)d_in[11];
    float*       out         = (float*)d_out;

    // One-time host-side stream/event setup (no device allocations).
    static cudaStream_t s2 = nullptr;
    static cudaEvent_t evFork = nullptr, evJoin = nullptr;
    static cudaEvent_t evDeg = nullptr, evDegDone = nullptr;
    if (s2 == nullptr) {
        cudaStreamCreateWithFlags(&s2, cudaStreamNonBlocking);
        cudaEventCreateWithFlags(&evFork, cudaEventDisableTiming);
        cudaEventCreateWithFlags(&evJoin, cudaEventDisableTiming);
        cudaEventCreateWithFlags(&evDeg, cudaEventDisableTiming);
        cudaEventCreateWithFlags(&evDegDone, cudaEventDisableTiming);
    }

    // Fork: dense front-end (k_wc, k_x0) on s2; CSR build on the main stream.
    cudaEventRecord(evFork, 0);
    cudaStreamWaitEvent(s2, evFork, 0);
    k_wc<<<16, 128, 0, s2>>>(W1, b1, W2, b2);
    k_x0<<<(NN + 63) / 64, 256, 0, s2>>>(features);
    cudaEventRecord(evJoin, s2);

    // CSR build (main stream; g_deg arrives zeroed — static init on the
    // first eager run, s2 tail-zero on every subsequent run/replay).
    k_hist<<<(EE + 1023) / 1024, 256>>>(edge_index);
    k_blocksum<<<NB, 256>>>();
    k_rowptr_zeropool<<<NB + 256, 256>>>();
    // g_deg's last reader is k_rowptr_zeropool: re-zero it on s2, overlapped
    // with scatter + propagation.
    cudaEventRecord(evDeg, 0);
    cudaStreamWaitEvent(s2, evDeg, 0);
    k_zero_deg<<<NB, 256, 0, s2>>>();
    cudaEventRecord(evDegDone, s2);
    k_scatter<<<(EE + 1023) / 1024, 256>>>(edge_index, edge_weight);

    // Join before propagation (needs both CSR and x0/ah16)
    cudaStreamWaitEvent(0, evJoin, 0);

    // APPNP propagation (scaled fp16 iterate); final step fuses the pooling.
    __half2* xa = nullptr; __half2* xb = nullptr;
    cudaGetSymbolAddress((void**)&xa, g_x16a);
    cudaGetSymbolAddress((void**)&xb, g_x16b);

    const int prop_grid = (NN * 32 + 255) / 256;   // 6250
    const __half2* cur = xa;
    float hs = 1.0f;
    for (int k = 0; k < KSTEPS; ++k) {
        hs *= 0.25f;                     // 4^-(k+1); ALPHA folded into g_ah16
        int fin = (k == KSTEPS - 1);
        __half2* nxt = (k % 2 == 0) ? xb : xa;
        k_prop<<<prop_grid, 256>>>(cur, fin ? nullptr : nxt, hs, fin, batch);
        cur = nxt;
    }

    k_head<<<GG, 128>>>(V0w, V0b, V1w, V1b, out);
    cudaStreamWaitEvent(0, evDegDone, 0);   // graph ends after deg re-zero too
}